// round 3
// baseline (speedup 1.0000x reference)
#include <cuda_runtime.h>
#include <math.h>

// Fused: H1 = relu(X@W1+b1); H2 = relu(H1@W2+b2); Y = H2@W3+b3; g = silu(Y);
// out[graph] += g  (graph_idx sorted -> in-tile segmented reduction, few atomics)
//
// Per CTA: 64 node rows. H1 (64x512 fp32) lives in SMEM (padded stride 513).
// Weights streamed in 32x128 tiles from L2. GEMM2 and GEMM3 are fused through a
// 64x128 SMEM chunk buffer so H2 is never materialized globally.
//
// NOTE: graph_idx arrives as int32 (JAX default x64-disabled demotes int64).

#define TILE_M 64

__global__ void __launch_bounds__(256, 1)
mlp_fused_kernel(const float* __restrict__ X,
                 const int* __restrict__ gidx,
                 const float* __restrict__ W1, const float* __restrict__ b1,
                 const float* __restrict__ W2, const float* __restrict__ b2,
                 const float* __restrict__ W3, const float* __restrict__ b3,
                 float* __restrict__ out, int N)
{
    extern __shared__ float smem[];
    float* H1s = smem;                      // [64][513]  (pad -> conflict-free LDS)
    float* Xs  = H1s + 64 * 513;            // [64][33]
    float* Ws  = Xs  + 64 * 33;             // [32][128]  (weight tile staging)
    float* H2c = Ws  + 32 * 128;            // [64][129]  (H2 chunk / g buffer)
    int*   gids = (int*)(H2c + 64 * 129);   // [64]

    const int t   = threadIdx.x;
    const int tx  = t & 15;                 // 16 col-groups of 8
    const int ty  = t >> 4;                 // 16 row-groups of 4
    const int row0 = blockIdx.x * TILE_M;

    if (t < TILE_M) {
        int gr = row0 + t;
        gids[t] = (gr < N) ? gidx[gr] : -1;
    }

    // ================= GEMM1: H1 = relu(X @ W1 + b1), K = 256 =================
    for (int nc = 0; nc < 4; ++nc) {                 // 4 chunks of 128 cols
        float acc[4][8];
        #pragma unroll
        for (int i = 0; i < 4; ++i)
            #pragma unroll
            for (int j = 0; j < 8; ++j) acc[i][j] = 0.f;

        for (int kt = 0; kt < 8; ++kt) {             // 8 k-tiles of 32
            // X tile [64][32]
            #pragma unroll
            for (int u = 0; u < 8; ++u) {
                int i = t + u * 256;
                int r = i >> 5, c = i & 31;
                int gr = row0 + r;
                Xs[r * 33 + c] = (gr < N) ? X[(size_t)gr * 256 + (kt * 32 + c)] : 0.f;
            }
            // W1 tile [32][128]
            #pragma unroll
            for (int u = 0; u < 4; ++u) {
                int i = t + u * 256;
                int k = i >> 5, j4 = i & 31;
                float4 v = *(const float4*)&W1[(size_t)(kt * 32 + k) * 512 + nc * 128 + j4 * 4];
                *(float4*)&Ws[k * 128 + j4 * 4] = v;
            }
            __syncthreads();
            #pragma unroll
            for (int k = 0; k < 32; ++k) {
                float a[4];
                #pragma unroll
                for (int i = 0; i < 4; ++i) a[i] = Xs[(ty * 4 + i) * 33 + k];
                float4 bv0 = *(const float4*)&Ws[k * 128 + tx * 8];
                float4 bv1 = *(const float4*)&Ws[k * 128 + tx * 8 + 4];
                float b[8] = {bv0.x, bv0.y, bv0.z, bv0.w, bv1.x, bv1.y, bv1.z, bv1.w};
                #pragma unroll
                for (int i = 0; i < 4; ++i)
                    #pragma unroll
                    for (int j = 0; j < 8; ++j)
                        acc[i][j] = fmaf(a[i], b[j], acc[i][j]);
            }
            __syncthreads();
        }
        // bias + relu -> H1s
        #pragma unroll
        for (int j = 0; j < 8; ++j) {
            float bb = b1[nc * 128 + tx * 8 + j];
            #pragma unroll
            for (int i = 0; i < 4; ++i) {
                float v = acc[i][j] + bb;
                H1s[(ty * 4 + i) * 513 + nc * 128 + tx * 8 + j] = v > 0.f ? v : 0.f;
            }
        }
    }
    __syncthreads();

    // ======== GEMM2 (K=512) fused with GEMM3 (K=512 consumed in chunks) ========
    float yacc[4][8];
    #pragma unroll
    for (int i = 0; i < 4; ++i)
        #pragma unroll
        for (int j = 0; j < 8; ++j) yacc[i][j] = 0.f;

    for (int mc = 0; mc < 4; ++mc) {                 // H2 chunks of 128 cols
        float acc[4][8];
        #pragma unroll
        for (int i = 0; i < 4; ++i)
            #pragma unroll
            for (int j = 0; j < 8; ++j) acc[i][j] = 0.f;

        for (int kt = 0; kt < 16; ++kt) {            // K=512 in 32-tiles
            #pragma unroll
            for (int u = 0; u < 4; ++u) {
                int i = t + u * 256;
                int k = i >> 5, j4 = i & 31;
                float4 v = *(const float4*)&W2[(size_t)(kt * 32 + k) * 512 + mc * 128 + j4 * 4];
                *(float4*)&Ws[k * 128 + j4 * 4] = v;
            }
            __syncthreads();
            #pragma unroll
            for (int k = 0; k < 32; ++k) {
                float a[4];
                #pragma unroll
                for (int i = 0; i < 4; ++i) a[i] = H1s[(ty * 4 + i) * 513 + kt * 32 + k];
                float4 bv0 = *(const float4*)&Ws[k * 128 + tx * 8];
                float4 bv1 = *(const float4*)&Ws[k * 128 + tx * 8 + 4];
                float b[8] = {bv0.x, bv0.y, bv0.z, bv0.w, bv1.x, bv1.y, bv1.z, bv1.w};
                #pragma unroll
                for (int i = 0; i < 4; ++i)
                    #pragma unroll
                    for (int j = 0; j < 8; ++j)
                        acc[i][j] = fmaf(a[i], b[j], acc[i][j]);
            }
            __syncthreads();
        }
        // bias + relu -> H2 chunk
        #pragma unroll
        for (int j = 0; j < 8; ++j) {
            float bb = b2[mc * 128 + tx * 8 + j];
            #pragma unroll
            for (int i = 0; i < 4; ++i) {
                float v = acc[i][j] + bb;
                H2c[(ty * 4 + i) * 129 + tx * 8 + j] = v > 0.f ? v : 0.f;
            }
        }
        __syncthreads();

        // GEMM3 partial: yacc += H2c[64x128] @ W3[mc*128 .. +128][0..128]
        for (int kt = 0; kt < 4; ++kt) {
            #pragma unroll
            for (int u = 0; u < 4; ++u) {
                int i = t + u * 256;
                int k = i >> 5, j4 = i & 31;
                float4 v = *(const float4*)&W3[(size_t)(mc * 128 + kt * 32 + k) * 128 + j4 * 4];
                *(float4*)&Ws[k * 128 + j4 * 4] = v;
            }
            __syncthreads();
            #pragma unroll
            for (int k = 0; k < 32; ++k) {
                float a[4];
                #pragma unroll
                for (int i = 0; i < 4; ++i) a[i] = H2c[(ty * 4 + i) * 129 + kt * 32 + k];
                float4 bv0 = *(const float4*)&Ws[k * 128 + tx * 8];
                float4 bv1 = *(const float4*)&Ws[k * 128 + tx * 8 + 4];
                float b[8] = {bv0.x, bv0.y, bv0.z, bv0.w, bv1.x, bv1.y, bv1.z, bv1.w};
                #pragma unroll
                for (int i = 0; i < 4; ++i)
                    #pragma unroll
                    for (int j = 0; j < 8; ++j)
                        yacc[i][j] = fmaf(a[i], b[j], yacc[i][j]);
            }
            __syncthreads();
        }
    }

    // ================= epilogue: SiLU + segmented reduction =================
    #pragma unroll
    for (int j = 0; j < 8; ++j) {
        float bb = b3[tx * 8 + j];
        #pragma unroll
        for (int i = 0; i < 4; ++i) {
            float y = yacc[i][j] + bb;
            float g = y / (1.f + expf(-y));          // silu
            H2c[(ty * 4 + i) * 129 + tx * 8 + j] = g;
        }
    }
    __syncthreads();

    if (t < 128) {                                   // one thread per output column
        int cur = gids[0];
        float s = 0.f;
        #pragma unroll 1
        for (int r = 0; r < TILE_M; ++r) {
            int gi = gids[r];
            if (gi != cur) {
                if (cur >= 0) atomicAdd(&out[(size_t)cur * 128 + t], s);
                cur = gi; s = 0.f;
            }
            if (gi >= 0) s += H2c[r * 129 + t];
        }
        if (cur >= 0) atomicAdd(&out[(size_t)cur * 128 + t], s);
    }
}

__global__ void zero_out_kernel(float* out, int n)
{
    int i = blockIdx.x * blockDim.x + threadIdx.x;
    if (i < n) out[i] = 0.f;
}

extern "C" void kernel_launch(void* const* d_in, const int* in_sizes, int n_in,
                              void* d_out, int out_size)
{
    const float* X    = (const float*)d_in[0];
    const int*   gidx = (const int*)d_in[1];     // int32! (JAX x64 disabled)
    const float* W1   = (const float*)d_in[2];
    const float* b1   = (const float*)d_in[3];
    const float* W2   = (const float*)d_in[4];
    const float* b2   = (const float*)d_in[5];
    const float* W3   = (const float*)d_in[6];
    const float* b3   = (const float*)d_in[7];
    float* out = (float*)d_out;

    const int N = in_sizes[0] / 256;

    zero_out_kernel<<<(out_size + 255) / 256, 256>>>(out, out_size);

    const int smem_bytes = (64 * 513 + 64 * 33 + 32 * 128 + 64 * 129) * 4 + 64 * 4;
    cudaFuncSetAttribute(mlp_fused_kernel,
                         cudaFuncAttributeMaxDynamicSharedMemorySize, smem_bytes);

    const int blocks = (N + TILE_M - 1) / TILE_M;
    mlp_fused_kernel<<<blocks, 256, smem_bytes>>>(X, gidx, W1, b1, W2, b2, W3, b3, out, N);
}

// round 6
// speedup vs baseline: 2.7705x; 2.7705x over previous
#include <cuda_runtime.h>
#include <cuda_bf16.h>
#include <mma.h>
#include <math.h>
#include <cstdint>

using namespace nvcuda;

// ============================================================================
// WMMA bf16 3-term-split fused MLP + segment sum (no tcgen05: sm_103 baseline).
//   setup:  W{1,2,3}t = transpose + split(W) -> bf16 hi/lo, [N][K] K-major
//   kernA:  H1 = relu(X @ W1 + b1)                    -> g_H1_{hi,lo}
//   kernB:  H2 = relu(H1 @ W2 + b2) per 128-col chunk (SMEM only),
//           Y += H2chunk @ W3chunk  (fused, Y in registers),
//           g = silu(Y + b3), sorted segment-sum -> out (few atomics)
// Split: A@B ~= Ahi@Bhi + Ahi@Blo + Alo@Bhi  (dropped term ~2^-18)
// R6 fix: kernel-B tile loaders filled only rows 0..63 (p<2); need p<4.
// ============================================================================

#define NODES_PAD (3907 * 128)   // 500,096 >= 500,000

__device__ __nv_bfloat16 g_W1t_hi[512 * 256];
__device__ __nv_bfloat16 g_W1t_lo[512 * 256];
__device__ __nv_bfloat16 g_W2t_hi[512 * 512];
__device__ __nv_bfloat16 g_W2t_lo[512 * 512];
__device__ __nv_bfloat16 g_W3t_hi[128 * 512];
__device__ __nv_bfloat16 g_W3t_lo[128 * 512];
__device__ __nv_bfloat16 g_H1_hi[(size_t)NODES_PAD * 512];
__device__ __nv_bfloat16 g_H1_lo[(size_t)NODES_PAD * 512];

__device__ __forceinline__ void split2(float v, __nv_bfloat16& h, __nv_bfloat16& l) {
    h = __float2bfloat16(v);
    l = __float2bfloat16(v - __bfloat162float(h));
}

// ---------------- setup: transpose + split weights ----------------
__global__ void setup_weights(const float* __restrict__ W1, const float* __restrict__ W2,
                              const float* __restrict__ W3)
{
    int i = blockIdx.x * blockDim.x + threadIdx.x;
    __nv_bfloat16 h, l;
    if (i < 512 * 256) {                       // W1 [256K x 512N] -> W1t [512][256]
        int n = i >> 8, k = i & 255;
        split2(W1[k * 512 + n], h, l);
        g_W1t_hi[n * 256 + k] = h; g_W1t_lo[n * 256 + k] = l;
        return;
    }
    i -= 512 * 256;
    if (i < 512 * 512) {                       // W2 [512 x 512] -> W2t [512][512]
        int n = i >> 9, k = i & 511;
        split2(W2[k * 512 + n], h, l);
        g_W2t_hi[n * 512 + k] = h; g_W2t_lo[n * 512 + k] = l;
        return;
    }
    i -= 512 * 512;
    if (i < 128 * 512) {                       // W3 [512K x 128N] -> W3t [128][512]
        int n = i >> 9, k = i & 511;
        split2(W3[k * 128 + n], h, l);
        g_W3t_hi[n * 512 + k] = h; g_W3t_lo[n * 512 + k] = l;
    }
}

__global__ void zero_out_kernel(float* out, int n)
{
    int i = blockIdx.x * blockDim.x + threadIdx.x;
    if (i < n) out[i] = 0.f;
}

// ============================================================================
// Kernel A: H1 = relu(X @ W1 + b1)  (M-tile 128, N = 512 in 4 chunks of 128)
// ============================================================================
#define XS_LD  264   // 256 + 8 pad (bf16 elems)
#define WT_LD  72    // 64 + 8 pad

__global__ void __launch_bounds__(256, 1)
gemm1_kernel(const float* __restrict__ X, const float* __restrict__ b1, int Nn)
{
    extern __shared__ char smem[];
    __nv_bfloat16* Xh = (__nv_bfloat16*)smem;            // [128][264]
    __nv_bfloat16* Xl = Xh + 128 * XS_LD;
    __nv_bfloat16* Wh = Xl + 128 * XS_LD;                 // [128][72]
    __nv_bfloat16* Wl = Wh + 128 * WT_LD;
    float*         fbuf = (float*)(Wl + 128 * WT_LD);    // [128][64]

    const int t   = threadIdx.x;
    const int wid = t >> 5;
    const int wm  = wid & 3;          // 4 warps over M (32 rows each)
    const int wn  = wid >> 2;         // 2 warps over N (64 cols each)
    const int row0 = blockIdx.x * 128;

    // ---- load + split X (128 x 256 fp32) ----
    #pragma unroll 4
    for (int p = 0; p < 32; ++p) {
        int idx = t + p * 256;
        int r = idx >> 6, c4 = idx & 63;
        float4 v = (row0 + r < Nn) ? *(const float4*)(X + (size_t)(row0 + r) * 256 + c4 * 4)
                                   : make_float4(0.f, 0.f, 0.f, 0.f);
        float vv[4] = {v.x, v.y, v.z, v.w};
        #pragma unroll
        for (int q = 0; q < 4; ++q) {
            __nv_bfloat16 h, l; split2(vv[q], h, l);
            Xh[r * XS_LD + c4 * 4 + q] = h;
            Xl[r * XS_LD + c4 * 4 + q] = l;
        }
    }
    __syncthreads();

    for (int nc = 0; nc < 4; ++nc) {
        wmma::fragment<wmma::accumulator, 16, 16, 16, float> acc[2][4];
        #pragma unroll
        for (int i = 0; i < 2; ++i)
            #pragma unroll
            for (int j = 0; j < 4; ++j) wmma::fill_fragment(acc[i][j], 0.f);

        for (int kt = 0; kt < 4; ++kt) {
            // W1t tile [128 n][64 k] hi/lo
            #pragma unroll
            for (int p = 0; p < 4; ++p) {
                int idx = t + p * 256;
                int r = idx >> 3, c8 = idx & 7;
                *(uint4*)&Wh[r * WT_LD + c8 * 8] =
                    *(const uint4*)(g_W1t_hi + (size_t)(nc * 128 + r) * 256 + kt * 64 + c8 * 8);
                *(uint4*)&Wl[r * WT_LD + c8 * 8] =
                    *(const uint4*)(g_W1t_lo + (size_t)(nc * 128 + r) * 256 + kt * 64 + c8 * 8);
            }
            __syncthreads();
            #pragma unroll
            for (int ks = 0; ks < 4; ++ks) {
                wmma::fragment<wmma::matrix_a, 16, 16, 16, __nv_bfloat16, wmma::row_major> ah[2], al[2];
                wmma::fragment<wmma::matrix_b, 16, 16, 16, __nv_bfloat16, wmma::col_major> bh[4], bl[4];
                #pragma unroll
                for (int i = 0; i < 2; ++i) {
                    int off = (wm * 32 + i * 16) * XS_LD + kt * 64 + ks * 16;
                    wmma::load_matrix_sync(ah[i], Xh + off, XS_LD);
                    wmma::load_matrix_sync(al[i], Xl + off, XS_LD);
                }
                #pragma unroll
                for (int j = 0; j < 4; ++j) {
                    int off = (wn * 64 + j * 16) * WT_LD + ks * 16;
                    wmma::load_matrix_sync(bh[j], Wh + off, WT_LD);
                    wmma::load_matrix_sync(bl[j], Wl + off, WT_LD);
                }
                #pragma unroll
                for (int i = 0; i < 2; ++i)
                    #pragma unroll
                    for (int j = 0; j < 4; ++j) {
                        wmma::mma_sync(acc[i][j], ah[i], bh[j], acc[i][j]);
                        wmma::mma_sync(acc[i][j], ah[i], bl[j], acc[i][j]);
                        wmma::mma_sync(acc[i][j], al[i], bh[j], acc[i][j]);
                    }
            }
            __syncthreads();
        }
        // ---- epilogue: +b1, relu, split -> g_H1 (two 64-col passes) ----
        for (int h = 0; h < 2; ++h) {
            if (wn == h) {
                #pragma unroll
                for (int i = 0; i < 2; ++i)
                    #pragma unroll
                    for (int j = 0; j < 4; ++j)
                        wmma::store_matrix_sync(fbuf + (wm * 32 + i * 16) * 64 + j * 16,
                                                acc[i][j], 64, wmma::mem_row_major);
            }
            __syncthreads();
            int col0 = nc * 128 + h * 64;
            #pragma unroll 4
            for (int p = 0; p < 32; ++p) {
                int idx = t + p * 256;
                int r = idx >> 6, c = idx & 63;
                if (row0 + r < Nn) {
                    float v = fbuf[r * 64 + c] + b1[col0 + c];
                    v = v > 0.f ? v : 0.f;
                    __nv_bfloat16 hh, ll; split2(v, hh, ll);
                    g_H1_hi[(size_t)(row0 + r) * 512 + col0 + c] = hh;
                    g_H1_lo[(size_t)(row0 + r) * 512 + col0 + c] = ll;
                }
            }
            __syncthreads();
        }
    }
}

// ============================================================================
// Kernel B: H2 = relu(H1@W2+b2) per chunk; Y += H2c@W3c; silu; segment sum
// ============================================================================
#define P_LD 136     // 128 + 8 pad

__global__ void __launch_bounds__(256, 1)
gemm23_kernel(const int* __restrict__ gidx,
              const float* __restrict__ b2, const float* __restrict__ b3,
              float* __restrict__ out, int Nn)
{
    extern __shared__ char smem[];
    __nv_bfloat16* Hh  = (__nv_bfloat16*)smem;            // [128][72]
    __nv_bfloat16* Hl  = Hh  + 128 * WT_LD;
    __nv_bfloat16* Wh  = Hl  + 128 * WT_LD;               // [128][72]
    __nv_bfloat16* Wl  = Wh  + 128 * WT_LD;
    __nv_bfloat16* W3h = Wl  + 128 * WT_LD;               // [128][72]
    __nv_bfloat16* W3l = W3h + 128 * WT_LD;
    __nv_bfloat16* Ph  = W3l + 128 * WT_LD;               // [128][136]
    __nv_bfloat16* Pl  = Ph  + 128 * P_LD;
    float*         fbuf = (float*)(Pl + 128 * P_LD);      // [128][64]
    int*           gids = (int*)(fbuf + 128 * 64);        // [128]
    float*         gbuf = (float*)smem;                    // [128][128] reuses Hh..Wl

    const int t   = threadIdx.x;
    const int wid = t >> 5;
    const int wm  = wid & 3;
    const int wn  = wid >> 2;
    const int row0 = blockIdx.x * 128;

    if (t < 128) gids[t] = (row0 + t < Nn) ? gidx[row0 + t] : -1;

    wmma::fragment<wmma::accumulator, 16, 16, 16, float> Y[2][4];
    #pragma unroll
    for (int i = 0; i < 2; ++i)
        #pragma unroll
        for (int j = 0; j < 4; ++j) wmma::fill_fragment(Y[i][j], 0.f);

    for (int mc = 0; mc < 4; ++mc) {
        wmma::fragment<wmma::accumulator, 16, 16, 16, float> acc2[2][4];
        #pragma unroll
        for (int i = 0; i < 2; ++i)
            #pragma unroll
            for (int j = 0; j < 4; ++j) wmma::fill_fragment(acc2[i][j], 0.f);

        // ---- GEMM2 chunk: acc2 = H1 @ W2t[mc*128..+128][:] ----
        for (int kt = 0; kt < 8; ++kt) {
            #pragma unroll
            for (int p = 0; p < 4; ++p) {      // H1 tile [128 m][64 k]  (1024 items)
                int idx = t + p * 256;
                int r = idx >> 3, c8 = idx & 7;
                size_t src = (size_t)(row0 + r) * 512 + kt * 64 + c8 * 8;
                *(uint4*)&Hh[r * WT_LD + c8 * 8] = *(const uint4*)(g_H1_hi + src);
                *(uint4*)&Hl[r * WT_LD + c8 * 8] = *(const uint4*)(g_H1_lo + src);
            }
            #pragma unroll
            for (int p = 0; p < 4; ++p) {      // W2t tile [128 n][64 k]  (1024 items)
                int idx = t + p * 256;
                int r = idx >> 3, c8 = idx & 7;
                size_t src = (size_t)(mc * 128 + r) * 512 + kt * 64 + c8 * 8;
                *(uint4*)&Wh[r * WT_LD + c8 * 8] = *(const uint4*)(g_W2t_hi + src);
                *(uint4*)&Wl[r * WT_LD + c8 * 8] = *(const uint4*)(g_W2t_lo + src);
            }
            __syncthreads();
            #pragma unroll
            for (int ks = 0; ks < 4; ++ks) {
                wmma::fragment<wmma::matrix_a, 16, 16, 16, __nv_bfloat16, wmma::row_major> ah[2], al[2];
                wmma::fragment<wmma::matrix_b, 16, 16, 16, __nv_bfloat16, wmma::col_major> bh[4], bl[4];
                #pragma unroll
                for (int i = 0; i < 2; ++i) {
                    int off = (wm * 32 + i * 16) * WT_LD + ks * 16;
                    wmma::load_matrix_sync(ah[i], Hh + off, WT_LD);
                    wmma::load_matrix_sync(al[i], Hl + off, WT_LD);
                }
                #pragma unroll
                for (int j = 0; j < 4; ++j) {
                    int off = (wn * 64 + j * 16) * WT_LD + ks * 16;
                    wmma::load_matrix_sync(bh[j], Wh + off, WT_LD);
                    wmma::load_matrix_sync(bl[j], Wl + off, WT_LD);
                }
                #pragma unroll
                for (int i = 0; i < 2; ++i)
                    #pragma unroll
                    for (int j = 0; j < 4; ++j) {
                        wmma::mma_sync(acc2[i][j], ah[i], bh[j], acc2[i][j]);
                        wmma::mma_sync(acc2[i][j], ah[i], bl[j], acc2[i][j]);
                        wmma::mma_sync(acc2[i][j], al[i], bh[j], acc2[i][j]);
                    }
            }
            __syncthreads();
        }
        // ---- chunk epilogue: +b2, relu, split -> Ph/Pl ----
        for (int h = 0; h < 2; ++h) {
            if (wn == h) {
                #pragma unroll
                for (int i = 0; i < 2; ++i)
                    #pragma unroll
                    for (int j = 0; j < 4; ++j)
                        wmma::store_matrix_sync(fbuf + (wm * 32 + i * 16) * 64 + j * 16,
                                                acc2[i][j], 64, wmma::mem_row_major);
            }
            __syncthreads();
            #pragma unroll 4
            for (int p = 0; p < 32; ++p) {
                int idx = t + p * 256;
                int r = idx >> 6, c = idx & 63;
                float v = fbuf[r * 64 + c] + b2[mc * 128 + h * 64 + c];
                v = v > 0.f ? v : 0.f;
                __nv_bfloat16 hh, ll; split2(v, hh, ll);
                Ph[r * P_LD + h * 64 + c] = hh;
                Pl[r * P_LD + h * 64 + c] = ll;
            }
            __syncthreads();
        }
        // ---- GEMM3 partial: Y += Ph/Pl @ W3t[:, mc*128..+128] ----
        for (int kt3 = 0; kt3 < 2; ++kt3) {
            #pragma unroll
            for (int p = 0; p < 4; ++p) {      // W3t tile [128 n][64 k]  (1024 items)
                int idx = t + p * 256;
                int r = idx >> 3, c8 = idx & 7;
                size_t src = (size_t)r * 512 + mc * 128 + kt3 * 64 + c8 * 8;
                *(uint4*)&W3h[r * WT_LD + c8 * 8] = *(const uint4*)(g_W3t_hi + src);
                *(uint4*)&W3l[r * WT_LD + c8 * 8] = *(const uint4*)(g_W3t_lo + src);
            }
            __syncthreads();
            #pragma unroll
            for (int ks = 0; ks < 4; ++ks) {
                wmma::fragment<wmma::matrix_a, 16, 16, 16, __nv_bfloat16, wmma::row_major> ah[2], al[2];
                wmma::fragment<wmma::matrix_b, 16, 16, 16, __nv_bfloat16, wmma::col_major> bh[4], bl[4];
                #pragma unroll
                for (int i = 0; i < 2; ++i) {
                    int off = (wm * 32 + i * 16) * P_LD + kt3 * 64 + ks * 16;
                    wmma::load_matrix_sync(ah[i], Ph + off, P_LD);
                    wmma::load_matrix_sync(al[i], Pl + off, P_LD);
                }
                #pragma unroll
                for (int j = 0; j < 4; ++j) {
                    int off = (wn * 64 + j * 16) * WT_LD + ks * 16;
                    wmma::load_matrix_sync(bh[j], W3h + off, WT_LD);
                    wmma::load_matrix_sync(bl[j], W3l + off, WT_LD);
                }
                #pragma unroll
                for (int i = 0; i < 2; ++i)
                    #pragma unroll
                    for (int j = 0; j < 4; ++j) {
                        wmma::mma_sync(Y[i][j], ah[i], bh[j], Y[i][j]);
                        wmma::mma_sync(Y[i][j], ah[i], bl[j], Y[i][j]);
                        wmma::mma_sync(Y[i][j], al[i], bh[j], Y[i][j]);
                    }
            }
            __syncthreads();
        }
    }

    // ---- final: Y -> gbuf, +b3, silu, sorted segment reduce, atomics ----
    #pragma unroll
    for (int i = 0; i < 2; ++i)
        #pragma unroll
        for (int j = 0; j < 4; ++j)
            wmma::store_matrix_sync(gbuf + (wm * 32 + i * 16) * 128 + wn * 64 + j * 16,
                                    Y[i][j], 128, wmma::mem_row_major);
    __syncthreads();
    #pragma unroll 4
    for (int p = 0; p < 64; ++p) {
        int idx = t + p * 256;
        int r = idx >> 7, c = idx & 127;
        float y = gbuf[r * 128 + c] + b3[c];
        gbuf[r * 128 + c] = y / (1.f + expf(-y));
    }
    __syncthreads();

    if (t < 128) {
        int cur = gids[0];
        float s = 0.f;
        #pragma unroll 1
        for (int r = 0; r < 128; ++r) {
            int gi = gids[r];
            if (gi != cur) {
                if (cur >= 0) atomicAdd(&out[(size_t)cur * 128 + t], s);
                cur = gi; s = 0.f;
            }
            if (gi >= 0) s += gbuf[r * 128 + t];
        }
        if (cur >= 0) atomicAdd(&out[(size_t)cur * 128 + t], s);
    }
}

// ============================================================================
extern "C" void kernel_launch(void* const* d_in, const int* in_sizes, int n_in,
                              void* d_out, int out_size)
{
    const float* X    = (const float*)d_in[0];
    const int*   gidx = (const int*)d_in[1];     // int32 (JAX x64 disabled)
    const float* W1   = (const float*)d_in[2];
    const float* b1   = (const float*)d_in[3];
    const float* W2   = (const float*)d_in[4];
    const float* b2   = (const float*)d_in[5];
    const float* W3   = (const float*)d_in[6];
    const float* b3   = (const float*)d_in[7];
    float* out = (float*)d_out;

    const int Nn = in_sizes[0] / 256;
    const int blocks = (Nn + 127) / 128;

    zero_out_kernel<<<(out_size + 255) / 256, 256>>>(out, out_size);
    setup_weights<<<(512 * 256 + 512 * 512 + 128 * 512 + 255) / 256, 256>>>(W1, W2, W3);

    // kernel A smem: X hi/lo (2*128*264*2) + W tile hi/lo (2*128*72*2) + fbuf (128*64*4)
    const int smemA = 2 * 128 * XS_LD * 2 + 2 * 128 * WT_LD * 2 + 128 * 64 * 4;       // 204800
    // kernel B smem: 6 * [128][72] bf16 + 2 * [128][136] bf16 + fbuf + gids
    const int smemB = 6 * 128 * WT_LD * 2 + 2 * 128 * P_LD * 2 + 128 * 64 * 4 + 512;  // 213504
    cudaFuncSetAttribute(gemm1_kernel,  cudaFuncAttributeMaxDynamicSharedMemorySize, smemA);
    cudaFuncSetAttribute(gemm23_kernel, cudaFuncAttributeMaxDynamicSharedMemorySize, smemB);

    gemm1_kernel<<<blocks, 256, smemA>>>(X, b1, Nn);
    gemm23_kernel<<<blocks, 256, smemB>>>(gidx, b2, b3, out, Nn);
}